// round 14
// baseline (speedup 1.0000x reference)
#include <cuda_runtime.h>
#include <cuda_fp16.h>
#include <cstdint>
#include <math.h>

// Problem constants
static constexpr int B  = 4;
static constexpr int S  = 2048;
static constexpr int D  = 1024;
static constexpr int H  = 16;
static constexpr int M_ROWS = B * S;       // 8192

// Q pre-scale: (1/sqrt(64)) * log2(e)  -> scores arrive in log2 domain
#define QSCALE 0.18033688011112042f

// ---------------------------------------------------------------------------
// Scratch (device globals)
// ---------------------------------------------------------------------------
__device__ __half g_x16[M_ROWS * D];
__device__ __half g_q16[M_ROWS * D];
__device__ __half g_k16[M_ROWS * D];
__device__ __half g_v16[M_ROWS * D];
__device__ __half g_o16[M_ROWS * D];
__device__ __half g_w[4][D * D];           // wq,wk,wv contiguous => N=3072 view; [3]=wo

struct __align__(8) h4 { __half v[4]; };

// ---------------------------------------------------------------------------
// Portable-PTX helpers (compute_103-safe)
// ---------------------------------------------------------------------------
__device__ __forceinline__ uint32_t smem_to_u32(const void* p) {
    uint32_t a;
    asm("{ .reg .u64 tmp; cvta.to.shared.u64 tmp, %1; cvt.u32.u64 %0, tmp; }"
        : "=r"(a) : "l"(p));
    return a;
}
__device__ __forceinline__ void ldsm4(uint32_t* r, uint32_t addr) {
    asm volatile("ldmatrix.sync.aligned.m8n8.x4.shared.b16 {%0,%1,%2,%3}, [%4];"
        : "=r"(r[0]), "=r"(r[1]), "=r"(r[2]), "=r"(r[3]) : "r"(addr));
}
__device__ __forceinline__ void ldsm4t(uint32_t* r, uint32_t addr) {
    asm volatile("ldmatrix.sync.aligned.m8n8.x4.trans.shared.b16 {%0,%1,%2,%3}, [%4];"
        : "=r"(r[0]), "=r"(r[1]), "=r"(r[2]), "=r"(r[3]) : "r"(addr));
}
__device__ __forceinline__ void mma16816(float* c, const uint32_t* a, const uint32_t* b) {
    asm volatile("mma.sync.aligned.m16n8k16.row.col.f32.f16.f16.f32 "
        "{%0,%1,%2,%3}, {%4,%5,%6,%7}, {%8,%9}, {%0,%1,%2,%3};"
        : "+f"(c[0]), "+f"(c[1]), "+f"(c[2]), "+f"(c[3])
        : "r"(a[0]), "r"(a[1]), "r"(a[2]), "r"(a[3]), "r"(b[0]), "r"(b[1]));
}
__device__ __forceinline__ void cp_async16(uint32_t dst, const void* src) {
    asm volatile("cp.async.cg.shared.global [%0], [%1], 16;" :: "r"(dst), "l"(src));
}
#define CP_COMMIT() asm volatile("cp.async.commit_group;" ::: "memory")
#define CP_WAIT(n)  asm volatile("cp.async.wait_group %0;" :: "n"(n) : "memory")
#define SWZ128(off) ((off) ^ (((off) >> 3) & 0x70))
#define SWZ64(off)  ((off) ^ (((off) >> 3) & 0x30))

__device__ __forceinline__ uint32_t packh2(float a, float b) {
    __half2 p = __floats2half2_rn(a, b);
    return *(uint32_t*)&p;
}
__device__ __forceinline__ uint32_t ex2h2(uint32_t x) {
    uint32_t r;
    asm("ex2.approx.f16x2 %0, %1;" : "=r"(r) : "r"(x));
    return r;
}

// ---------------------------------------------------------------------------
// Fused preprocessing: grid.z 0..3 -> transpose+round weight z; z==4 -> convert x
// ---------------------------------------------------------------------------
__global__ __launch_bounds__(256) void prep_kernel(
    const float* __restrict__ W0, const float* __restrict__ W1,
    const float* __restrict__ W2, const float* __restrict__ W3,
    __half* __restrict__ T,
    const float4* __restrict__ X, h4* __restrict__ X16)
{
    const int z = blockIdx.z;
    if (z == 4) {
        const int bid = blockIdx.y * gridDim.x + blockIdx.x;   // 0..1023
        const int t = threadIdx.y * 32 + threadIdx.x;          // 0..255
        int base = bid * 2048 + t;
#pragma unroll
        for (int it = 0; it < 8; it++) {
            float4 v = X[base + it * 256];
            h4 h;
            h.v[0] = __float2half_rn(v.x);
            h.v[1] = __float2half_rn(v.y);
            h.v[2] = __float2half_rn(v.z);
            h.v[3] = __float2half_rn(v.w);
            X16[base + it * 256] = h;
        }
        return;
    }
    __shared__ float tile[32][33];
    const float* W = (z == 0) ? W0 : (z == 1) ? W1 : (z == 2) ? W2 : W3;
    __half* Tz = T + (size_t)z * D * D;
    const int bx = blockIdx.x * 32;
    const int by = blockIdx.y * 32;
    const int tx = threadIdx.x, ty = threadIdx.y;
#pragma unroll
    for (int i = ty; i < 32; i += 8)
        tile[i][tx] = W[(size_t)(by + i) * D + bx + tx];
    __syncthreads();
#pragma unroll
    for (int i = ty; i < 32; i += 8)
        Tz[(size_t)(bx + i) * D + by + tx] = __float2half_rn(tile[tx][i]);
}

// ---------------------------------------------------------------------------
// Shared GEMM mainloop: 128x128 CTA tile, BK=32, SW64 smem, 6-stage pipeline
// (5 load-groups in flight ~ 1280 cyc of latency coverage), one barrier/iter.
// Per stage (16 KB): A(8K) B(8K); 6 stages = 96 KB; 2 CTAs/SM (192 KB).
// ---------------------------------------------------------------------------
static constexpr int GEMM_STAGES = 6;
static constexpr int GEMM_SMEM = GEMM_STAGES * 16384;   // 98304

__device__ __forceinline__ void gemm_issue_chunk(
    uint32_t sbase, const __half* const* srcs, int t, int c)
{
    const int k0 = c * 32;
    const uint32_t base = (uint32_t)(c % GEMM_STAGES) * 16384u;
#pragma unroll
    for (int ld = 0; ld < 4; ld++) {
        const int tile = ld >> 1;
        const int j = t + 256 * (ld & 1);      // 0..511
        const int r = j >> 2, c16 = j & 3;     // 128 rows x 4 16B-chunks
        const __half* src = srcs[tile] + (size_t)r * 1024 + k0 + c16 * 8;
        const uint32_t dst = sbase + base + (uint32_t)tile * 8192u +
                             SWZ64((uint32_t)(r * 64 + c16 * 16));
        cp_async16(dst, src);
    }
    CP_COMMIT();
}

__device__ __forceinline__ void gemm_mainloop(
    uint32_t sbase, const __half* const* srcs, int t, float acc[2][8][4])
{
    const int wid = t >> 5, lid = t & 31;
    const int warp_m = wid & 3;
    const int warp_n = wid >> 2;

    // Prologue: 5 groups in flight
#pragma unroll
    for (int s = 0; s < GEMM_STAGES - 1; s++)
        gemm_issue_chunk(sbase, srcs, t, s);

    const int a_row  = lid & 15;
    const int a_colb = (lid >> 4) * 16;
    const int b_row  = ((lid >> 4) & 1) * 8 + (lid & 7);
    const int b_colb = ((lid >> 3) & 1) * 16;

    for (int c = 0; c < 32; c++) {
        CP_WAIT(GEMM_STAGES - 2);   // stage c resident
        __syncthreads();
        // Issue stage c+5 into buffer (c-1)%6 — drained by all warps (barrier).
        if (c + GEMM_STAGES - 1 < 32)
            gemm_issue_chunk(sbase, srcs, t, c + GEMM_STAGES - 1);

        const uint32_t a_b = sbase + (uint32_t)(c % GEMM_STAGES) * 16384u;
        const uint32_t b_b = a_b + 8192u;

#pragma unroll
        for (int ks = 0; ks < 2; ks++) {
            const int kb = ks * 32;
            uint32_t af[2][4];
#pragma unroll
            for (int mt = 0; mt < 2; mt++) {
                const uint32_t ro = (uint32_t)((warp_m * 32 + mt * 16 + a_row) * 64
                                               + kb + a_colb);
                ldsm4(af[mt], a_b + SWZ64(ro));
            }
#pragma unroll
            for (int g = 0; g < 4; g++) {
                const uint32_t ro = (uint32_t)((warp_n * 64 + g * 16 + b_row) * 64
                                               + kb + b_colb);
                uint32_t bf[4];
                ldsm4(bf, b_b + SWZ64(ro));
#pragma unroll
                for (int mt = 0; mt < 2; mt++)
#pragma unroll
                    for (int ns = 0; ns < 2; ns++)
                        mma16816(acc[mt][g * 2 + ns], af[mt], &bf[ns * 2]);
            }
        }
    }
}

// ---------------------------------------------------------------------------
// Fused QKV GEMM: N=3072. Q scaled by QSCALE (1/8 * log2 e); fp16 outputs.
// grid = (24, 64)
// ---------------------------------------------------------------------------
__global__ __launch_bounds__(256, 2)
void gemm_qkv_kernel(const __half* __restrict__ X16,
                     const __half* __restrict__ W,
                     const float* __restrict__ bq,
                     const float* __restrict__ bk,
                     const float* __restrict__ bv,
                     __half* __restrict__ Q16,
                     __half* __restrict__ K16, __half* __restrict__ V16)
{
    extern __shared__ __align__(1024) char smem[];
    const uint32_t sbase = smem_to_u32(smem);
    const int t = threadIdx.x;
    const int wid = t >> 5, lid = t & 31;
    const int warp_m = wid & 3, warp_n = wid >> 2;
    const int m0 = blockIdx.y * 128;
    const int n0g = blockIdx.x * 128;          // 0..2944
    const int seg = n0g >> 10;                 // 0=Q, 1=K, 2=V
    const int n0 = n0g & 1023;

    const float* bias = (seg == 0) ? bq : (seg == 1) ? bk : bv;
    __half* Cd = (seg == 0) ? Q16 : (seg == 1) ? K16 : V16;
    const float scale = (seg == 0) ? QSCALE : 1.0f;

    const __half* srcs[2];
    srcs[0] = X16 + (size_t)m0 * 1024;
    srcs[1] = W   + (size_t)n0g * 1024;

    float acc[2][8][4];
#pragma unroll
    for (int mt = 0; mt < 2; mt++)
#pragma unroll
        for (int nt = 0; nt < 8; nt++)
#pragma unroll
            for (int j = 0; j < 4; j++) acc[mt][nt][j] = 0.f;

    gemm_mainloop(sbase, srcs, t, acc);

#pragma unroll
    for (int mt = 0; mt < 2; mt++) {
        const int r0 = m0 + warp_m * 32 + mt * 16 + (lid >> 2);
#pragma unroll
        for (int nt = 0; nt < 8; nt++) {
            const int col = n0 + warp_n * 64 + nt * 8 + (lid & 3) * 2;
            float2 bv2 = *(const float2*)&bias[col];
            const float* a4 = acc[mt][nt];
            *(uint32_t*)&Cd[(size_t)r0 * 1024 + col] =
                packh2((a4[0] + bv2.x) * scale, (a4[1] + bv2.y) * scale);
            *(uint32_t*)&Cd[(size_t)(r0 + 8) * 1024 + col] =
                packh2((a4[2] + bv2.x) * scale, (a4[3] + bv2.y) * scale);
        }
    }
}

// ---------------------------------------------------------------------------
// Out-proj GEMM: N=1024, fp32 out + bias. grid = (8, 64)
// ---------------------------------------------------------------------------
__global__ __launch_bounds__(256, 2)
void gemm_out_kernel(const __half* __restrict__ A16,
                     const __half* __restrict__ W,
                     const float* __restrict__ bias,
                     float* __restrict__ C)
{
    extern __shared__ __align__(1024) char smem[];
    const uint32_t sbase = smem_to_u32(smem);
    const int t = threadIdx.x;
    const int wid = t >> 5, lid = t & 31;
    const int warp_m = wid & 3, warp_n = wid >> 2;
    const int m0 = blockIdx.y * 128;
    const int n0 = blockIdx.x * 128;

    const __half* srcs[2];
    srcs[0] = A16 + (size_t)m0 * 1024;
    srcs[1] = W   + (size_t)n0 * 1024;

    float acc[2][8][4];
#pragma unroll
    for (int mt = 0; mt < 2; mt++)
#pragma unroll
        for (int nt = 0; nt < 8; nt++)
#pragma unroll
            for (int j = 0; j < 4; j++) acc[mt][nt][j] = 0.f;

    gemm_mainloop(sbase, srcs, t, acc);

#pragma unroll
    for (int mt = 0; mt < 2; mt++) {
        const int r0 = m0 + warp_m * 32 + mt * 16 + (lid >> 2);
#pragma unroll
        for (int nt = 0; nt < 8; nt++) {
            const int col = n0 + warp_n * 64 + nt * 8 + (lid & 3) * 2;
            float2 bv2 = *(const float2*)&bias[col];
            const float* a4 = acc[mt][nt];
            *(float2*)&C[(size_t)r0 * 1024 + col] =
                make_float2(a4[0] + bv2.x, a4[1] + bv2.y);
            *(float2*)&C[(size_t)(r0 + 8) * 1024 + col] =
                make_float2(a4[2] + bv2.x, a4[3] + bv2.y);
        }
    }
}

// ---------------------------------------------------------------------------
// HMMA attention (R10 configuration — measured 164.3 us). UNCHANGED.
// ---------------------------------------------------------------------------
static constexpr int ATT_SMEM = 16384 + 3 * 16384;   // 65536

__global__ __launch_bounds__(256, 2)
void attn_hmma_kernel(const __half* __restrict__ Q16,
                      const __half* __restrict__ K16,
                      const __half* __restrict__ V16,
                      __half* __restrict__ O16)
{
    extern __shared__ __align__(1024) char smem[];
    const uint32_t sbase = smem_to_u32(smem);
    const int t = threadIdx.x;
    const int wid = t >> 5, lid = t & 31;
    const int qt = blockIdx.x * 128;
    const int bh = blockIdx.y;
    const int b = bh >> 4, h = bh & 15;
    const int grow = b * S + qt;
    const int hoff = h * 64;

#pragma unroll
    for (int ld = 0; ld < 4; ld++) {
        const int j = t + 256 * ld;           // 0..1023
        const int r = j >> 3, c16 = j & 7;
        const __half* src = Q16 + (size_t)(grow + r) * 1024 + hoff + c16 * 8;
        const uint32_t dst = sbase + SWZ128((uint32_t)(r * 128 + c16 * 16));
        cp_async16(dst, src);
    }
    CP_COMMIT();

    const __half* ksrc = K16 + (size_t)b * S * 1024 + hoff;
    const __half* vsrc = V16 + (size_t)b * S * 1024 + hoff;

    auto issue_kv = [&](int c) {
        const int k0 = c * 64;
        const uint32_t base = 16384u + (uint32_t)(c % 3) * 16384u;
#pragma unroll
        for (int ld = 0; ld < 4; ld++) {
            const int j = t + 256 * ld;       // 0..1023
            const int tile = j >> 9;          // 0=K, 1=V
            const int jj = j & 511;
            const int r = jj >> 3, c16 = jj & 7;
            const __half* src = (tile ? vsrc : ksrc) + (size_t)(k0 + r) * 1024 + c16 * 8;
            const uint32_t dst = sbase + base + (uint32_t)tile * 8192u +
                                 SWZ128((uint32_t)(r * 128 + c16 * 16));
            cp_async16(dst, src);
        }
        CP_COMMIT();
    };

    issue_kv(0);
    issue_kv(1);
    CP_WAIT(2);          // Q group done
    __syncthreads();

    const int a_row = lid & 15;
    const int a_col = (lid >> 4) * 16;
    uint32_t qf[4][4];
#pragma unroll
    for (int ks = 0; ks < 4; ks++) {
        const uint32_t ro = (uint32_t)((wid * 16 + a_row) * 128 + ks * 32 + a_col);
        ldsm4(qf[ks], sbase + SWZ128(ro));
    }

    float o[8][4];
#pragma unroll
    for (int j = 0; j < 8; j++)
#pragma unroll
        for (int q = 0; q < 4; q++) o[j][q] = 0.f;
    float lacc[4] = {0.f, 0.f, 0.f, 0.f};
    const uint32_t ones_b[2] = {0x3C003C00u, 0x3C003C00u};

    const int b_row = ((lid >> 4) & 1) * 8 + (lid & 7);
    const int b_col = ((lid >> 3) & 1) * 16;
    const int g2 = lid >> 3;
    const int vr = (g2 & 1) * 8 + (lid & 7);
    const int vcol = (g2 >> 1) * 8;

    for (int c = 0; c < 32; c++) {
        if (c + 1 < 32) CP_WAIT(1); else CP_WAIT(0);
        __syncthreads();

        const uint32_t kb = sbase + 16384u + (uint32_t)(c % 3) * 16384u;
        const uint32_t vb = kb + 8192u;

        float st[8][4];
#pragma unroll
        for (int j = 0; j < 8; j++)
#pragma unroll
            for (int q = 0; q < 4; q++) st[j][q] = 0.f;

#pragma unroll
        for (int ks = 0; ks < 4; ks++) {
#pragma unroll
            for (int g = 0; g < 4; g++) {
                const uint32_t ro = (uint32_t)((g * 16 + b_row) * 128 + ks * 32 + b_col);
                uint32_t kf[4];
                ldsm4(kf, kb + SWZ128(ro));
#pragma unroll
                for (int ns = 0; ns < 2; ns++)
                    mma16816(st[g * 2 + ns], qf[ks], &kf[ns * 2]);
            }
        }

#pragma unroll
        for (int ks = 0; ks < 4; ks++) {
            uint32_t ph[4];
#pragma unroll
            for (int half = 0; half < 2; half++) {
                const float* sA = st[2 * ks + half];
                ph[half * 2 + 0] = ex2h2(packh2(sA[0], sA[1]));
                ph[half * 2 + 1] = ex2h2(packh2(sA[2], sA[3]));
            }
            mma16816(lacc, ph, ones_b);
#pragma unroll
            for (int nt = 0; nt < 4; nt++) {
                const uint32_t ro = (uint32_t)((ks * 16 + vr) * 128 + (nt * 16 + vcol) * 2);
                uint32_t vf[4];
                ldsm4t(vf, vb + SWZ128(ro));
#pragma unroll
                for (int ns = 0; ns < 2; ns++)
                    mma16816(o[nt * 2 + ns], ph, &vf[ns * 2]);
            }
        }

        if (c + 2 < 32) issue_kv(c + 2);
    }

    const float inv0 = 1.0f / lacc[0];
    const float inv1 = 1.0f / lacc[2];
    const int gr0 = grow + wid * 16 + (lid >> 2);
    const int gr1 = gr0 + 8;
#pragma unroll
    for (int j = 0; j < 8; j++) {
        const int col = hoff + j * 8 + (lid & 3) * 2;
        *(uint32_t*)&O16[(size_t)gr0 * 1024 + col] =
            packh2(o[j][0] * inv0, o[j][1] * inv0);
        *(uint32_t*)&O16[(size_t)gr1 * 1024 + col] =
            packh2(o[j][2] * inv1, o[j][3] * inv1);
    }
}

// ---------------------------------------------------------------------------
// Row-wise LayerNorm, in place
// ---------------------------------------------------------------------------
__global__ __launch_bounds__(256) void ln_kernel(
    float* __restrict__ y, const float* __restrict__ g, const float* __restrict__ bb)
{
    const int row = blockIdx.x;
    const int t = threadIdx.x;
    float4* y4 = (float4*)(y + (size_t)row * D);
    float4 v = y4[t];
    float s = v.x + v.y + v.z + v.w;
    float q = v.x * v.x + v.y * v.y + v.z * v.z + v.w * v.w;
#pragma unroll
    for (int msk = 16; msk >= 1; msk >>= 1) {
        s += __shfl_xor_sync(0xffffffffu, s, msk);
        q += __shfl_xor_sync(0xffffffffu, q, msk);
    }
    __shared__ float rs[8], rq[8];
    int wid = t >> 5, lane = t & 31;
    if (lane == 0) { rs[wid] = s; rq[wid] = q; }
    __syncthreads();
    if (t == 0) {
        float ts = 0.f, tq = 0.f;
#pragma unroll
        for (int i = 0; i < 8; i++) { ts += rs[i]; tq += rq[i]; }
        rs[0] = ts; rq[0] = tq;
    }
    __syncthreads();
    float mu  = rs[0] * (1.0f / D);
    float var = rq[0] * (1.0f / D) - mu * mu;
    float rinv = rsqrtf(var + 1e-12f);
    float4 gg = ((const float4*)g)[t];
    float4 bv = ((const float4*)bb)[t];
    float4 ov;
    ov.x = (v.x - mu) * rinv * gg.x + bv.x;
    ov.y = (v.y - mu) * rinv * gg.y + bv.y;
    ov.z = (v.z - mu) * rinv * gg.z + bv.z;
    ov.w = (v.w - mu) * rinv * gg.w + bv.w;
    y4[t] = ov;
}

// ---------------------------------------------------------------------------
extern "C" void kernel_launch(void* const* d_in, const int* in_sizes, int n_in,
                              void* d_out, int out_size)
{
    const float* x   = (const float*)d_in[0];
    const float* wq  = (const float*)d_in[1];
    const float* bq  = (const float*)d_in[2];
    const float* wk  = (const float*)d_in[3];
    const float* bk  = (const float*)d_in[4];
    const float* wv  = (const float*)d_in[5];
    const float* bv  = (const float*)d_in[6];
    const float* wo  = (const float*)d_in[7];
    const float* bo  = (const float*)d_in[8];
    const float* lng = (const float*)d_in[9];
    const float* lnb = (const float*)d_in[10];
    float* out = (float*)d_out;

    __half *x16, *q16, *k16, *v16, *o16, *w;
    cudaGetSymbolAddress((void**)&x16, g_x16);
    cudaGetSymbolAddress((void**)&q16, g_q16);
    cudaGetSymbolAddress((void**)&k16, g_k16);
    cudaGetSymbolAddress((void**)&v16, g_v16);
    cudaGetSymbolAddress((void**)&o16, g_o16);
    cudaGetSymbolAddress((void**)&w, g_w);

    // Fused preprocessing: 4 weight transposes + x convert in ONE launch
    dim3 pthr(32, 8), pgrd(D / 32, D / 32, 5);
    prep_kernel<<<pgrd, pthr>>>(wq, wk, wv, wo, w, (const float4*)x, (h4*)x16);

    cudaFuncSetAttribute(gemm_qkv_kernel,
                         cudaFuncAttributeMaxDynamicSharedMemorySize, GEMM_SMEM);
    cudaFuncSetAttribute(gemm_out_kernel,
                         cudaFuncAttributeMaxDynamicSharedMemorySize, GEMM_SMEM);

    gemm_qkv_kernel<<<dim3(3 * D / 128, M_ROWS / 128), 256, GEMM_SMEM>>>(
        x16, w, bq, bk, bv, q16, k16, v16);

    cudaFuncSetAttribute(attn_hmma_kernel,
                         cudaFuncAttributeMaxDynamicSharedMemorySize, ATT_SMEM);
    attn_hmma_kernel<<<dim3(S / 128, B * H), 256, ATT_SMEM>>>(
        q16, k16, v16, o16);

    gemm_out_kernel<<<dim3(D / 128, M_ROWS / 128), 256, GEMM_SMEM>>>(
        o16, w + 3 * (size_t)D * D, bo, out);

    ln_kernel<<<M_ROWS, 256>>>(out, lng, lnb);
}

// round 15
// speedup vs baseline: 1.0497x; 1.0497x over previous
#include <cuda_runtime.h>
#include <cuda_fp16.h>
#include <cstdint>
#include <math.h>

// Problem constants
static constexpr int B  = 4;
static constexpr int S  = 2048;
static constexpr int D  = 1024;
static constexpr int H  = 16;
static constexpr int M_ROWS = B * S;       // 8192

// Q pre-scale: (1/sqrt(64)) * log2(e)  -> scores arrive in log2 domain
#define QSCALE 0.18033688011112042f

// ---------------------------------------------------------------------------
// Scratch (device globals)
// ---------------------------------------------------------------------------
__device__ __half g_x16[M_ROWS * D];
__device__ __half g_q16[M_ROWS * D];
__device__ __half g_k16[M_ROWS * D];
__device__ __half g_v16[M_ROWS * D];
__device__ __half g_o16[M_ROWS * D];
__device__ __half g_w[4][D * D];           // wq,wk,wv contiguous => N=3072 view; [3]=wo

struct __align__(8) h4 { __half v[4]; };

// ---------------------------------------------------------------------------
// Portable-PTX helpers (compute_103-safe)
// ---------------------------------------------------------------------------
__device__ __forceinline__ uint32_t smem_to_u32(const void* p) {
    uint32_t a;
    asm("{ .reg .u64 tmp; cvta.to.shared.u64 tmp, %1; cvt.u32.u64 %0, tmp; }"
        : "=r"(a) : "l"(p));
    return a;
}
__device__ __forceinline__ void ldsm4(uint32_t* r, uint32_t addr) {
    asm volatile("ldmatrix.sync.aligned.m8n8.x4.shared.b16 {%0,%1,%2,%3}, [%4];"
        : "=r"(r[0]), "=r"(r[1]), "=r"(r[2]), "=r"(r[3]) : "r"(addr));
}
__device__ __forceinline__ void ldsm4t(uint32_t* r, uint32_t addr) {
    asm volatile("ldmatrix.sync.aligned.m8n8.x4.trans.shared.b16 {%0,%1,%2,%3}, [%4];"
        : "=r"(r[0]), "=r"(r[1]), "=r"(r[2]), "=r"(r[3]) : "r"(addr));
}
__device__ __forceinline__ void mma16816(float* c, const uint32_t* a, const uint32_t* b) {
    asm volatile("mma.sync.aligned.m16n8k16.row.col.f32.f16.f16.f32 "
        "{%0,%1,%2,%3}, {%4,%5,%6,%7}, {%8,%9}, {%0,%1,%2,%3};"
        : "+f"(c[0]), "+f"(c[1]), "+f"(c[2]), "+f"(c[3])
        : "r"(a[0]), "r"(a[1]), "r"(a[2]), "r"(a[3]), "r"(b[0]), "r"(b[1]));
}
__device__ __forceinline__ void cp_async16(uint32_t dst, const void* src) {
    asm volatile("cp.async.cg.shared.global [%0], [%1], 16;" :: "r"(dst), "l"(src));
}
#define CP_COMMIT() asm volatile("cp.async.commit_group;" ::: "memory")
#define CP_WAIT(n)  asm volatile("cp.async.wait_group %0;" :: "n"(n) : "memory")
#define SWZ128(off) ((off) ^ (((off) >> 3) & 0x70))
#define SWZ64(off)  ((off) ^ (((off) >> 3) & 0x30))

__device__ __forceinline__ uint32_t packh2(float a, float b) {
    __half2 p = __floats2half2_rn(a, b);
    return *(uint32_t*)&p;
}
__device__ __forceinline__ uint32_t ex2h2(uint32_t x) {
    uint32_t r;
    asm("ex2.approx.f16x2 %0, %1;" : "=r"(r) : "r"(x));
    return r;
}

// ---------------------------------------------------------------------------
// Fused preprocessing: grid.z 0..3 -> transpose+round weight z; z==4 -> convert x
// ---------------------------------------------------------------------------
__global__ __launch_bounds__(256) void prep_kernel(
    const float* __restrict__ W0, const float* __restrict__ W1,
    const float* __restrict__ W2, const float* __restrict__ W3,
    __half* __restrict__ T,
    const float4* __restrict__ X, h4* __restrict__ X16)
{
    const int z = blockIdx.z;
    if (z == 4) {
        const int bid = blockIdx.y * gridDim.x + blockIdx.x;   // 0..1023
        const int t = threadIdx.y * 32 + threadIdx.x;          // 0..255
        int base = bid * 2048 + t;
#pragma unroll
        for (int it = 0; it < 8; it++) {
            float4 v = X[base + it * 256];
            h4 h;
            h.v[0] = __float2half_rn(v.x);
            h.v[1] = __float2half_rn(v.y);
            h.v[2] = __float2half_rn(v.z);
            h.v[3] = __float2half_rn(v.w);
            X16[base + it * 256] = h;
        }
        return;
    }
    __shared__ float tile[32][33];
    const float* W = (z == 0) ? W0 : (z == 1) ? W1 : (z == 2) ? W2 : W3;
    __half* Tz = T + (size_t)z * D * D;
    const int bx = blockIdx.x * 32;
    const int by = blockIdx.y * 32;
    const int tx = threadIdx.x, ty = threadIdx.y;
#pragma unroll
    for (int i = ty; i < 32; i += 8)
        tile[i][tx] = W[(size_t)(by + i) * D + bx + tx];
    __syncthreads();
#pragma unroll
    for (int i = ty; i < 32; i += 8)
        Tz[(size_t)(bx + i) * D + by + tx] = __float2half_rn(tile[tx][i]);
}

// ---------------------------------------------------------------------------
// Shared GEMM mainloop (R13-measured): 128x128 CTA tile, BK=32, SW64 smem,
// 3-stage pipeline, ONE __syncthreads per iteration, issue-after-consume.
// Per stage (16 KB): A(8K) B(8K); 3 stages = 48 KB.
// ---------------------------------------------------------------------------
static constexpr int GEMM_SMEM = 3 * 16384;   // 49152

__device__ __forceinline__ void gemm_issue_chunk(
    uint32_t sbase, const __half* const* srcs, int t, int c)
{
    const int k0 = c * 32;
    const uint32_t base = (uint32_t)(c % 3) * 16384u;
#pragma unroll
    for (int ld = 0; ld < 4; ld++) {
        const int tile = ld >> 1;
        const int j = t + 256 * (ld & 1);      // 0..511
        const int r = j >> 2, c16 = j & 3;     // 128 rows x 4 16B-chunks
        const __half* src = srcs[tile] + (size_t)r * 1024 + k0 + c16 * 8;
        const uint32_t dst = sbase + base + (uint32_t)tile * 8192u +
                             SWZ64((uint32_t)(r * 64 + c16 * 16));
        cp_async16(dst, src);
    }
    CP_COMMIT();
}

__device__ __forceinline__ void gemm_mainloop(
    uint32_t sbase, const __half* const* srcs, int t, float acc[2][8][4])
{
    const int wid = t >> 5, lid = t & 31;
    const int warp_m = wid & 3;
    const int warp_n = wid >> 2;

    gemm_issue_chunk(sbase, srcs, t, 0);
    gemm_issue_chunk(sbase, srcs, t, 1);

    const int a_row  = lid & 15;
    const int a_colb = (lid >> 4) * 16;
    const int b_row  = ((lid >> 4) & 1) * 8 + (lid & 7);
    const int b_colb = ((lid >> 3) & 1) * 16;

    for (int c = 0; c < 32; c++) {
        if (c + 1 < 32) CP_WAIT(1); else CP_WAIT(0);
        __syncthreads();

        const uint32_t a_b = sbase + (uint32_t)(c % 3) * 16384u;
        const uint32_t b_b = a_b + 8192u;

#pragma unroll
        for (int ks = 0; ks < 2; ks++) {
            const int kb = ks * 32;
            uint32_t af[2][4];
#pragma unroll
            for (int mt = 0; mt < 2; mt++) {
                const uint32_t ro = (uint32_t)((warp_m * 32 + mt * 16 + a_row) * 64
                                               + kb + a_colb);
                ldsm4(af[mt], a_b + SWZ64(ro));
            }
#pragma unroll
            for (int g = 0; g < 4; g++) {
                const uint32_t ro = (uint32_t)((warp_n * 64 + g * 16 + b_row) * 64
                                               + kb + b_colb);
                uint32_t bf[4];
                ldsm4(bf, b_b + SWZ64(ro));
#pragma unroll
                for (int mt = 0; mt < 2; mt++)
#pragma unroll
                    for (int ns = 0; ns < 2; ns++)
                        mma16816(acc[mt][g * 2 + ns], af[mt], &bf[ns * 2]);
            }
        }
        if (c + 2 < 32) gemm_issue_chunk(sbase, srcs, t, c + 2);
    }
}

// ---------------------------------------------------------------------------
// Fused QKV GEMM: N=3072. Q scaled by QSCALE (1/8 * log2 e); fp16 outputs.
// grid = (24, 64)
// ---------------------------------------------------------------------------
__global__ __launch_bounds__(256, 2)
void gemm_qkv_kernel(const __half* __restrict__ X16,
                     const __half* __restrict__ W,
                     const float* __restrict__ bq,
                     const float* __restrict__ bk,
                     const float* __restrict__ bv,
                     __half* __restrict__ Q16,
                     __half* __restrict__ K16, __half* __restrict__ V16)
{
    extern __shared__ __align__(1024) char smem[];
    const uint32_t sbase = smem_to_u32(smem);
    const int t = threadIdx.x;
    const int wid = t >> 5, lid = t & 31;
    const int warp_m = wid & 3, warp_n = wid >> 2;
    const int m0 = blockIdx.y * 128;
    const int n0g = blockIdx.x * 128;          // 0..2944
    const int seg = n0g >> 10;                 // 0=Q, 1=K, 2=V
    const int n0 = n0g & 1023;

    const float* bias = (seg == 0) ? bq : (seg == 1) ? bk : bv;
    __half* Cd = (seg == 0) ? Q16 : (seg == 1) ? K16 : V16;
    const float scale = (seg == 0) ? QSCALE : 1.0f;

    const __half* srcs[2];
    srcs[0] = X16 + (size_t)m0 * 1024;
    srcs[1] = W   + (size_t)n0g * 1024;

    float acc[2][8][4];
#pragma unroll
    for (int mt = 0; mt < 2; mt++)
#pragma unroll
        for (int nt = 0; nt < 8; nt++)
#pragma unroll
            for (int j = 0; j < 4; j++) acc[mt][nt][j] = 0.f;

    gemm_mainloop(sbase, srcs, t, acc);

#pragma unroll
    for (int mt = 0; mt < 2; mt++) {
        const int r0 = m0 + warp_m * 32 + mt * 16 + (lid >> 2);
#pragma unroll
        for (int nt = 0; nt < 8; nt++) {
            const int col = n0 + warp_n * 64 + nt * 8 + (lid & 3) * 2;
            float2 bv2 = *(const float2*)&bias[col];
            const float* a4 = acc[mt][nt];
            *(uint32_t*)&Cd[(size_t)r0 * 1024 + col] =
                packh2((a4[0] + bv2.x) * scale, (a4[1] + bv2.y) * scale);
            *(uint32_t*)&Cd[(size_t)(r0 + 8) * 1024 + col] =
                packh2((a4[2] + bv2.x) * scale, (a4[3] + bv2.y) * scale);
        }
    }
}

// ---------------------------------------------------------------------------
// Out-proj GEMM: N=1024, fp32 out + bias. grid = (8, 64)
// ---------------------------------------------------------------------------
__global__ __launch_bounds__(256, 2)
void gemm_out_kernel(const __half* __restrict__ A16,
                     const __half* __restrict__ W,
                     const float* __restrict__ bias,
                     float* __restrict__ C)
{
    extern __shared__ __align__(1024) char smem[];
    const uint32_t sbase = smem_to_u32(smem);
    const int t = threadIdx.x;
    const int wid = t >> 5, lid = t & 31;
    const int warp_m = wid & 3, warp_n = wid >> 2;
    const int m0 = blockIdx.y * 128;
    const int n0 = blockIdx.x * 128;

    const __half* srcs[2];
    srcs[0] = A16 + (size_t)m0 * 1024;
    srcs[1] = W   + (size_t)n0 * 1024;

    float acc[2][8][4];
#pragma unroll
    for (int mt = 0; mt < 2; mt++)
#pragma unroll
        for (int nt = 0; nt < 8; nt++)
#pragma unroll
            for (int j = 0; j < 4; j++) acc[mt][nt][j] = 0.f;

    gemm_mainloop(sbase, srcs, t, acc);

#pragma unroll
    for (int mt = 0; mt < 2; mt++) {
        const int r0 = m0 + warp_m * 32 + mt * 16 + (lid >> 2);
#pragma unroll
        for (int nt = 0; nt < 8; nt++) {
            const int col = n0 + warp_n * 64 + nt * 8 + (lid & 3) * 2;
            float2 bv2 = *(const float2*)&bias[col];
            const float* a4 = acc[mt][nt];
            *(float2*)&C[(size_t)r0 * 1024 + col] =
                make_float2(a4[0] + bv2.x, a4[1] + bv2.y);
            *(float2*)&C[(size_t)(r0 + 8) * 1024 + col] =
                make_float2(a4[2] + bv2.x, a4[3] + bv2.y);
        }
    }
}

// ---------------------------------------------------------------------------
// HMMA attention (R10 configuration — measured 164.3 us). UNCHANGED.
// ---------------------------------------------------------------------------
static constexpr int ATT_SMEM = 16384 + 3 * 16384;   // 65536

__global__ __launch_bounds__(256, 2)
void attn_hmma_kernel(const __half* __restrict__ Q16,
                      const __half* __restrict__ K16,
                      const __half* __restrict__ V16,
                      __half* __restrict__ O16)
{
    extern __shared__ __align__(1024) char smem[];
    const uint32_t sbase = smem_to_u32(smem);
    const int t = threadIdx.x;
    const int wid = t >> 5, lid = t & 31;
    const int qt = blockIdx.x * 128;
    const int bh = blockIdx.y;
    const int b = bh >> 4, h = bh & 15;
    const int grow = b * S + qt;
    const int hoff = h * 64;

#pragma unroll
    for (int ld = 0; ld < 4; ld++) {
        const int j = t + 256 * ld;           // 0..1023
        const int r = j >> 3, c16 = j & 7;
        const __half* src = Q16 + (size_t)(grow + r) * 1024 + hoff + c16 * 8;
        const uint32_t dst = sbase + SWZ128((uint32_t)(r * 128 + c16 * 16));
        cp_async16(dst, src);
    }
    CP_COMMIT();

    const __half* ksrc = K16 + (size_t)b * S * 1024 + hoff;
    const __half* vsrc = V16 + (size_t)b * S * 1024 + hoff;

    auto issue_kv = [&](int c) {
        const int k0 = c * 64;
        const uint32_t base = 16384u + (uint32_t)(c % 3) * 16384u;
#pragma unroll
        for (int ld = 0; ld < 4; ld++) {
            const int j = t + 256 * ld;       // 0..1023
            const int tile = j >> 9;          // 0=K, 1=V
            const int jj = j & 511;
            const int r = jj >> 3, c16 = jj & 7;
            const __half* src = (tile ? vsrc : ksrc) + (size_t)(k0 + r) * 1024 + c16 * 8;
            const uint32_t dst = sbase + base + (uint32_t)tile * 8192u +
                                 SWZ128((uint32_t)(r * 128 + c16 * 16));
            cp_async16(dst, src);
        }
        CP_COMMIT();
    };

    issue_kv(0);
    issue_kv(1);
    CP_WAIT(2);          // Q group done
    __syncthreads();

    const int a_row = lid & 15;
    const int a_col = (lid >> 4) * 16;
    uint32_t qf[4][4];
#pragma unroll
    for (int ks = 0; ks < 4; ks++) {
        const uint32_t ro = (uint32_t)((wid * 16 + a_row) * 128 + ks * 32 + a_col);
        ldsm4(qf[ks], sbase + SWZ128(ro));
    }

    float o[8][4];
#pragma unroll
    for (int j = 0; j < 8; j++)
#pragma unroll
        for (int q = 0; q < 4; q++) o[j][q] = 0.f;
    float lacc[4] = {0.f, 0.f, 0.f, 0.f};
    const uint32_t ones_b[2] = {0x3C003C00u, 0x3C003C00u};

    const int b_row = ((lid >> 4) & 1) * 8 + (lid & 7);
    const int b_col = ((lid >> 3) & 1) * 16;
    const int g2 = lid >> 3;
    const int vr = (g2 & 1) * 8 + (lid & 7);
    const int vcol = (g2 >> 1) * 8;

    for (int c = 0; c < 32; c++) {
        if (c + 1 < 32) CP_WAIT(1); else CP_WAIT(0);
        __syncthreads();

        const uint32_t kb = sbase + 16384u + (uint32_t)(c % 3) * 16384u;
        const uint32_t vb = kb + 8192u;

        float st[8][4];
#pragma unroll
        for (int j = 0; j < 8; j++)
#pragma unroll
            for (int q = 0; q < 4; q++) st[j][q] = 0.f;

#pragma unroll
        for (int ks = 0; ks < 4; ks++) {
#pragma unroll
            for (int g = 0; g < 4; g++) {
                const uint32_t ro = (uint32_t)((g * 16 + b_row) * 128 + ks * 32 + b_col);
                uint32_t kf[4];
                ldsm4(kf, kb + SWZ128(ro));
#pragma unroll
                for (int ns = 0; ns < 2; ns++)
                    mma16816(st[g * 2 + ns], qf[ks], &kf[ns * 2]);
            }
        }

#pragma unroll
        for (int ks = 0; ks < 4; ks++) {
            uint32_t ph[4];
#pragma unroll
            for (int half = 0; half < 2; half++) {
                const float* sA = st[2 * ks + half];
                ph[half * 2 + 0] = ex2h2(packh2(sA[0], sA[1]));
                ph[half * 2 + 1] = ex2h2(packh2(sA[2], sA[3]));
            }
            mma16816(lacc, ph, ones_b);
#pragma unroll
            for (int nt = 0; nt < 4; nt++) {
                const uint32_t ro = (uint32_t)((ks * 16 + vr) * 128 + (nt * 16 + vcol) * 2);
                uint32_t vf[4];
                ldsm4t(vf, vb + SWZ128(ro));
#pragma unroll
                for (int ns = 0; ns < 2; ns++)
                    mma16816(o[nt * 2 + ns], ph, &vf[ns * 2]);
            }
        }

        if (c + 2 < 32) issue_kv(c + 2);
    }

    const float inv0 = 1.0f / lacc[0];
    const float inv1 = 1.0f / lacc[2];
    const int gr0 = grow + wid * 16 + (lid >> 2);
    const int gr1 = gr0 + 8;
#pragma unroll
    for (int j = 0; j < 8; j++) {
        const int col = hoff + j * 8 + (lid & 3) * 2;
        *(uint32_t*)&O16[(size_t)gr0 * 1024 + col] =
            packh2(o[j][0] * inv0, o[j][1] * inv0);
        *(uint32_t*)&O16[(size_t)gr1 * 1024 + col] =
            packh2(o[j][2] * inv1, o[j][3] * inv1);
    }
}

// ---------------------------------------------------------------------------
// Row-wise LayerNorm, warp-per-row (no barriers, no smem).
// grid = M_ROWS/8 blocks x 256 threads (8 warps); lane k owns float4 k,k+32,...
// ---------------------------------------------------------------------------
__global__ __launch_bounds__(256) void ln_kernel(
    float* __restrict__ y, const float* __restrict__ g, const float* __restrict__ bb)
{
    const int wid = threadIdx.x >> 5, lane = threadIdx.x & 31;
    const int row = blockIdx.x * 8 + wid;
    float4* y4 = (float4*)(y + (size_t)row * D);

    float4 v[8];
    float s = 0.f, q = 0.f;
#pragma unroll
    for (int k = 0; k < 8; k++) {
        v[k] = y4[lane + 32 * k];
        s += v[k].x + v[k].y + v[k].z + v[k].w;
        q += v[k].x * v[k].x + v[k].y * v[k].y + v[k].z * v[k].z + v[k].w * v[k].w;
    }
#pragma unroll
    for (int msk = 16; msk >= 1; msk >>= 1) {
        s += __shfl_xor_sync(0xffffffffu, s, msk);
        q += __shfl_xor_sync(0xffffffffu, q, msk);
    }
    const float mu  = s * (1.0f / D);
    const float var = q * (1.0f / D) - mu * mu;
    const float rinv = rsqrtf(var + 1e-12f);

    const float4* g4 = (const float4*)g;
    const float4* b4 = (const float4*)bb;
#pragma unroll
    for (int k = 0; k < 8; k++) {
        float4 gg = g4[lane + 32 * k];
        float4 bv = b4[lane + 32 * k];
        float4 ov;
        ov.x = (v[k].x - mu) * rinv * gg.x + bv.x;
        ov.y = (v[k].y - mu) * rinv * gg.y + bv.y;
        ov.z = (v[k].z - mu) * rinv * gg.z + bv.z;
        ov.w = (v[k].w - mu) * rinv * gg.w + bv.w;
        y4[lane + 32 * k] = ov;
    }
}

// ---------------------------------------------------------------------------
extern "C" void kernel_launch(void* const* d_in, const int* in_sizes, int n_in,
                              void* d_out, int out_size)
{
    const float* x   = (const float*)d_in[0];
    const float* wq  = (const float*)d_in[1];
    const float* bq  = (const float*)d_in[2];
    const float* wk  = (const float*)d_in[3];
    const float* bk  = (const float*)d_in[4];
    const float* wv  = (const float*)d_in[5];
    const float* bv  = (const float*)d_in[6];
    const float* wo  = (const float*)d_in[7];
    const float* bo  = (const float*)d_in[8];
    const float* lng = (const float*)d_in[9];
    const float* lnb = (const float*)d_in[10];
    float* out = (float*)d_out;

    __half *x16, *q16, *k16, *v16, *o16, *w;
    cudaGetSymbolAddress((void**)&x16, g_x16);
    cudaGetSymbolAddress((void**)&q16, g_q16);
    cudaGetSymbolAddress((void**)&k16, g_k16);
    cudaGetSymbolAddress((void**)&v16, g_v16);
    cudaGetSymbolAddress((void**)&o16, g_o16);
    cudaGetSymbolAddress((void**)&w, g_w);

    // Fused preprocessing: 4 weight transposes + x convert in ONE launch
    dim3 pthr(32, 8), pgrd(D / 32, D / 32, 5);
    prep_kernel<<<pgrd, pthr>>>(wq, wk, wv, wo, w, (const float4*)x, (h4*)x16);

    cudaFuncSetAttribute(gemm_qkv_kernel,
                         cudaFuncAttributeMaxDynamicSharedMemorySize, GEMM_SMEM);
    cudaFuncSetAttribute(gemm_out_kernel,
                         cudaFuncAttributeMaxDynamicSharedMemorySize, GEMM_SMEM);

    gemm_qkv_kernel<<<dim3(3 * D / 128, M_ROWS / 128), 256, GEMM_SMEM>>>(
        x16, w, bq, bk, bv, q16, k16, v16);

    cudaFuncSetAttribute(attn_hmma_kernel,
                         cudaFuncAttributeMaxDynamicSharedMemorySize, ATT_SMEM);
    attn_hmma_kernel<<<dim3(S / 128, B * H), 256, ATT_SMEM>>>(
        q16, k16, v16, o16);

    gemm_out_kernel<<<dim3(D / 128, M_ROWS / 128), 256, GEMM_SMEM>>>(
        o16, w + 3 * (size_t)D * D, bo, out);

    ln_kernel<<<M_ROWS / 8, 256>>>(out, lng, lnb);
}

// round 16
// speedup vs baseline: 1.0749x; 1.0240x over previous
#include <cuda_runtime.h>
#include <cuda_fp16.h>
#include <cstdint>
#include <math.h>

// Problem constants
static constexpr int B  = 4;
static constexpr int S  = 2048;
static constexpr int D  = 1024;
static constexpr int H  = 16;
static constexpr int M_ROWS = B * S;       // 8192

// Q pre-scale: (1/sqrt(64)) * log2(e)  -> scores arrive in log2 domain
#define QSCALE 0.18033688011112042f

// ---------------------------------------------------------------------------
// Scratch (device globals)
// ---------------------------------------------------------------------------
__device__ __half g_x16[M_ROWS * D];
__device__ __half g_q16[M_ROWS * D];
__device__ __half g_k16[M_ROWS * D];
__device__ __half g_v16[M_ROWS * D];
__device__ __half g_o16[M_ROWS * D];
__device__ __half g_w[4][D * D];           // wq,wk,wv contiguous => N=3072 view; [3]=wo

struct __align__(8) h4 { __half v[4]; };

// ---------------------------------------------------------------------------
// Portable-PTX helpers (compute_103-safe)
// ---------------------------------------------------------------------------
__device__ __forceinline__ uint32_t smem_to_u32(const void* p) {
    uint32_t a;
    asm("{ .reg .u64 tmp; cvta.to.shared.u64 tmp, %1; cvt.u32.u64 %0, tmp; }"
        : "=r"(a) : "l"(p));
    return a;
}
__device__ __forceinline__ void ldsm4(uint32_t* r, uint32_t addr) {
    asm volatile("ldmatrix.sync.aligned.m8n8.x4.shared.b16 {%0,%1,%2,%3}, [%4];"
        : "=r"(r[0]), "=r"(r[1]), "=r"(r[2]), "=r"(r[3]) : "r"(addr));
}
__device__ __forceinline__ void ldsm4t(uint32_t* r, uint32_t addr) {
    asm volatile("ldmatrix.sync.aligned.m8n8.x4.trans.shared.b16 {%0,%1,%2,%3}, [%4];"
        : "=r"(r[0]), "=r"(r[1]), "=r"(r[2]), "=r"(r[3]) : "r"(addr));
}
__device__ __forceinline__ void mma16816(float* c, const uint32_t* a, const uint32_t* b) {
    asm volatile("mma.sync.aligned.m16n8k16.row.col.f32.f16.f16.f32 "
        "{%0,%1,%2,%3}, {%4,%5,%6,%7}, {%8,%9}, {%0,%1,%2,%3};"
        : "+f"(c[0]), "+f"(c[1]), "+f"(c[2]), "+f"(c[3])
        : "r"(a[0]), "r"(a[1]), "r"(a[2]), "r"(a[3]), "r"(b[0]), "r"(b[1]));
}
__device__ __forceinline__ void cp_async16(uint32_t dst, const void* src) {
    asm volatile("cp.async.cg.shared.global [%0], [%1], 16;" :: "r"(dst), "l"(src));
}
#define CP_COMMIT() asm volatile("cp.async.commit_group;" ::: "memory")
#define CP_WAIT(n)  asm volatile("cp.async.wait_group %0;" :: "n"(n) : "memory")
#define SWZ128(off) ((off) ^ (((off) >> 3) & 0x70))

__device__ __forceinline__ uint32_t packh2(float a, float b) {
    __half2 p = __floats2half2_rn(a, b);
    return *(uint32_t*)&p;
}
__device__ __forceinline__ uint32_t ex2h2(uint32_t x) {
    uint32_t r;
    asm("ex2.approx.f16x2 %0, %1;" : "=r"(r) : "r"(x));
    return r;
}

// ---------------------------------------------------------------------------
// Fused preprocessing: grid.z 0..3 -> transpose+round weight z; z==4 -> convert x
// ---------------------------------------------------------------------------
__global__ __launch_bounds__(256) void prep_kernel(
    const float* __restrict__ W0, const float* __restrict__ W1,
    const float* __restrict__ W2, const float* __restrict__ W3,
    __half* __restrict__ T,
    const float4* __restrict__ X, h4* __restrict__ X16)
{
    const int z = blockIdx.z;
    if (z == 4) {
        const int bid = blockIdx.y * gridDim.x + blockIdx.x;   // 0..1023
        const int t = threadIdx.y * 32 + threadIdx.x;          // 0..255
        int base = bid * 2048 + t;
#pragma unroll
        for (int it = 0; it < 8; it++) {
            float4 v = X[base + it * 256];
            h4 h;
            h.v[0] = __float2half_rn(v.x);
            h.v[1] = __float2half_rn(v.y);
            h.v[2] = __float2half_rn(v.z);
            h.v[3] = __float2half_rn(v.w);
            X16[base + it * 256] = h;
        }
        return;
    }
    __shared__ float tile[32][33];
    const float* W = (z == 0) ? W0 : (z == 1) ? W1 : (z == 2) ? W2 : W3;
    __half* Tz = T + (size_t)z * D * D;
    const int bx = blockIdx.x * 32;
    const int by = blockIdx.y * 32;
    const int tx = threadIdx.x, ty = threadIdx.y;
#pragma unroll
    for (int i = ty; i < 32; i += 8)
        tile[i][tx] = W[(size_t)(by + i) * D + bx + tx];
    __syncthreads();
#pragma unroll
    for (int i = ty; i < 32; i += 8)
        Tz[(size_t)(bx + i) * D + by + tx] = __float2half_rn(tile[tx][i]);
}

// ---------------------------------------------------------------------------
// Shared GEMM mainloop: 128x128 CTA tile, BK=64 (SW128 rows), 3-stage
// pipeline, ONE __syncthreads per iteration, issue-after-consume.
// Per stage (32 KB): A(16K) B(16K); 3 stages = 96 KB; 2 CTAs/SM (192 KB).
// 16 iterations x (64 MMA + 24 LDSM) per warp.
// ---------------------------------------------------------------------------
static constexpr int GEMM_SMEM = 3 * 32768;   // 98304

__device__ __forceinline__ void gemm_issue_chunk(
    uint32_t sbase, const __half* const* srcs, int t, int c)
{
    const int k0 = c * 64;
    const uint32_t base = (uint32_t)(c % 3) * 32768u;
#pragma unroll
    for (int ld = 0; ld < 8; ld++) {
        const int j = t + 256 * ld;            // 0..2047
        const int tile = j >> 10;              // 0=A, 1=B
        const int jj = j & 1023;
        const int r = jj >> 3, c16 = jj & 7;   // 128 rows x 8 16B-chunks
        const __half* src = srcs[tile] + (size_t)r * 1024 + k0 + c16 * 8;
        const uint32_t dst = sbase + base + (uint32_t)tile * 16384u +
                             SWZ128((uint32_t)(r * 128 + c16 * 16));
        cp_async16(dst, src);
    }
    CP_COMMIT();
}

__device__ __forceinline__ void gemm_mainloop(
    uint32_t sbase, const __half* const* srcs, int t, float acc[2][8][4])
{
    const int wid = t >> 5, lid = t & 31;
    const int warp_m = wid & 3;
    const int warp_n = wid >> 2;

    gemm_issue_chunk(sbase, srcs, t, 0);
    gemm_issue_chunk(sbase, srcs, t, 1);

    const int a_row  = lid & 15;
    const int a_colb = (lid >> 4) * 16;
    const int b_row  = ((lid >> 4) & 1) * 8 + (lid & 7);
    const int b_colb = ((lid >> 3) & 1) * 16;

    for (int c = 0; c < 16; c++) {
        if (c + 1 < 16) CP_WAIT(1); else CP_WAIT(0);
        __syncthreads();

        const uint32_t a_b = sbase + (uint32_t)(c % 3) * 32768u;
        const uint32_t b_b = a_b + 16384u;

#pragma unroll
        for (int ks = 0; ks < 4; ks++) {
            const int kb = ks * 32;            // 16 cols = 32 bytes
            uint32_t af[2][4];
#pragma unroll
            for (int mt = 0; mt < 2; mt++) {
                const uint32_t ro = (uint32_t)((warp_m * 32 + mt * 16 + a_row) * 128
                                               + kb + a_colb);
                ldsm4(af[mt], a_b + SWZ128(ro));
            }
#pragma unroll
            for (int g = 0; g < 4; g++) {
                const uint32_t ro = (uint32_t)((warp_n * 64 + g * 16 + b_row) * 128
                                               + kb + b_colb);
                uint32_t bf[4];
                ldsm4(bf, b_b + SWZ128(ro));
#pragma unroll
                for (int mt = 0; mt < 2; mt++)
#pragma unroll
                    for (int ns = 0; ns < 2; ns++)
                        mma16816(acc[mt][g * 2 + ns], af[mt], &bf[ns * 2]);
            }
        }
        if (c + 2 < 16) gemm_issue_chunk(sbase, srcs, t, c + 2);
    }
}

// ---------------------------------------------------------------------------
// Fused QKV GEMM: N=3072. Q scaled by QSCALE (1/8 * log2 e); fp16 outputs.
// grid = (24, 64)
// ---------------------------------------------------------------------------
__global__ __launch_bounds__(256, 2)
void gemm_qkv_kernel(const __half* __restrict__ X16,
                     const __half* __restrict__ W,
                     const float* __restrict__ bq,
                     const float* __restrict__ bk,
                     const float* __restrict__ bv,
                     __half* __restrict__ Q16,
                     __half* __restrict__ K16, __half* __restrict__ V16)
{
    extern __shared__ __align__(1024) char smem[];
    const uint32_t sbase = smem_to_u32(smem);
    const int t = threadIdx.x;
    const int wid = t >> 5, lid = t & 31;
    const int warp_m = wid & 3, warp_n = wid >> 2;
    const int m0 = blockIdx.y * 128;
    const int n0g = blockIdx.x * 128;          // 0..2944
    const int seg = n0g >> 10;                 // 0=Q, 1=K, 2=V
    const int n0 = n0g & 1023;

    const float* bias = (seg == 0) ? bq : (seg == 1) ? bk : bv;
    __half* Cd = (seg == 0) ? Q16 : (seg == 1) ? K16 : V16;
    const float scale = (seg == 0) ? QSCALE : 1.0f;

    const __half* srcs[2];
    srcs[0] = X16 + (size_t)m0 * 1024;
    srcs[1] = W   + (size_t)n0g * 1024;

    float acc[2][8][4];
#pragma unroll
    for (int mt = 0; mt < 2; mt++)
#pragma unroll
        for (int nt = 0; nt < 8; nt++)
#pragma unroll
            for (int j = 0; j < 4; j++) acc[mt][nt][j] = 0.f;

    gemm_mainloop(sbase, srcs, t, acc);

#pragma unroll
    for (int mt = 0; mt < 2; mt++) {
        const int r0 = m0 + warp_m * 32 + mt * 16 + (lid >> 2);
#pragma unroll
        for (int nt = 0; nt < 8; nt++) {
            const int col = n0 + warp_n * 64 + nt * 8 + (lid & 3) * 2;
            float2 bv2 = *(const float2*)&bias[col];
            const float* a4 = acc[mt][nt];
            *(uint32_t*)&Cd[(size_t)r0 * 1024 + col] =
                packh2((a4[0] + bv2.x) * scale, (a4[1] + bv2.y) * scale);
            *(uint32_t*)&Cd[(size_t)(r0 + 8) * 1024 + col] =
                packh2((a4[2] + bv2.x) * scale, (a4[3] + bv2.y) * scale);
        }
    }
}

// ---------------------------------------------------------------------------
// Out-proj GEMM: N=1024, fp32 out + bias. grid = (8, 64)
// ---------------------------------------------------------------------------
__global__ __launch_bounds__(256, 2)
void gemm_out_kernel(const __half* __restrict__ A16,
                     const __half* __restrict__ W,
                     const float* __restrict__ bias,
                     float* __restrict__ C)
{
    extern __shared__ __align__(1024) char smem[];
    const uint32_t sbase = smem_to_u32(smem);
    const int t = threadIdx.x;
    const int wid = t >> 5, lid = t & 31;
    const int warp_m = wid & 3, warp_n = wid >> 2;
    const int m0 = blockIdx.y * 128;
    const int n0 = blockIdx.x * 128;

    const __half* srcs[2];
    srcs[0] = A16 + (size_t)m0 * 1024;
    srcs[1] = W   + (size_t)n0 * 1024;

    float acc[2][8][4];
#pragma unroll
    for (int mt = 0; mt < 2; mt++)
#pragma unroll
        for (int nt = 0; nt < 8; nt++)
#pragma unroll
            for (int j = 0; j < 4; j++) acc[mt][nt][j] = 0.f;

    gemm_mainloop(sbase, srcs, t, acc);

#pragma unroll
    for (int mt = 0; mt < 2; mt++) {
        const int r0 = m0 + warp_m * 32 + mt * 16 + (lid >> 2);
#pragma unroll
        for (int nt = 0; nt < 8; nt++) {
            const int col = n0 + warp_n * 64 + nt * 8 + (lid & 3) * 2;
            float2 bv2 = *(const float2*)&bias[col];
            const float* a4 = acc[mt][nt];
            *(float2*)&C[(size_t)r0 * 1024 + col] =
                make_float2(a4[0] + bv2.x, a4[1] + bv2.y);
            *(float2*)&C[(size_t)(r0 + 8) * 1024 + col] =
                make_float2(a4[2] + bv2.x, a4[3] + bv2.y);
        }
    }
}

// ---------------------------------------------------------------------------
// HMMA attention (R10 configuration — measured 164.3 us). UNCHANGED.
// ---------------------------------------------------------------------------
static constexpr int ATT_SMEM = 16384 + 3 * 16384;   // 65536

__global__ __launch_bounds__(256, 2)
void attn_hmma_kernel(const __half* __restrict__ Q16,
                      const __half* __restrict__ K16,
                      const __half* __restrict__ V16,
                      __half* __restrict__ O16)
{
    extern __shared__ __align__(1024) char smem[];
    const uint32_t sbase = smem_to_u32(smem);
    const int t = threadIdx.x;
    const int wid = t >> 5, lid = t & 31;
    const int qt = blockIdx.x * 128;
    const int bh = blockIdx.y;
    const int b = bh >> 4, h = bh & 15;
    const int grow = b * S + qt;
    const int hoff = h * 64;

#pragma unroll
    for (int ld = 0; ld < 4; ld++) {
        const int j = t + 256 * ld;           // 0..1023
        const int r = j >> 3, c16 = j & 7;
        const __half* src = Q16 + (size_t)(grow + r) * 1024 + hoff + c16 * 8;
        const uint32_t dst = sbase + SWZ128((uint32_t)(r * 128 + c16 * 16));
        cp_async16(dst, src);
    }
    CP_COMMIT();

    const __half* ksrc = K16 + (size_t)b * S * 1024 + hoff;
    const __half* vsrc = V16 + (size_t)b * S * 1024 + hoff;

    auto issue_kv = [&](int c) {
        const int k0 = c * 64;
        const uint32_t base = 16384u + (uint32_t)(c % 3) * 16384u;
#pragma unroll
        for (int ld = 0; ld < 4; ld++) {
            const int j = t + 256 * ld;       // 0..1023
            const int tile = j >> 9;          // 0=K, 1=V
            const int jj = j & 511;
            const int r = jj >> 3, c16 = jj & 7;
            const __half* src = (tile ? vsrc : ksrc) + (size_t)(k0 + r) * 1024 + c16 * 8;
            const uint32_t dst = sbase + base + (uint32_t)tile * 8192u +
                                 SWZ128((uint32_t)(r * 128 + c16 * 16));
            cp_async16(dst, src);
        }
        CP_COMMIT();
    };

    issue_kv(0);
    issue_kv(1);
    CP_WAIT(2);          // Q group done
    __syncthreads();

    const int a_row = lid & 15;
    const int a_col = (lid >> 4) * 16;
    uint32_t qf[4][4];
#pragma unroll
    for (int ks = 0; ks < 4; ks++) {
        const uint32_t ro = (uint32_t)((wid * 16 + a_row) * 128 + ks * 32 + a_col);
        ldsm4(qf[ks], sbase + SWZ128(ro));
    }

    float o[8][4];
#pragma unroll
    for (int j = 0; j < 8; j++)
#pragma unroll
        for (int q = 0; q < 4; q++) o[j][q] = 0.f;
    float lacc[4] = {0.f, 0.f, 0.f, 0.f};
    const uint32_t ones_b[2] = {0x3C003C00u, 0x3C003C00u};

    const int b_row = ((lid >> 4) & 1) * 8 + (lid & 7);
    const int b_col = ((lid >> 3) & 1) * 16;
    const int g2 = lid >> 3;
    const int vr = (g2 & 1) * 8 + (lid & 7);
    const int vcol = (g2 >> 1) * 8;

    for (int c = 0; c < 32; c++) {
        if (c + 1 < 32) CP_WAIT(1); else CP_WAIT(0);
        __syncthreads();

        const uint32_t kb = sbase + 16384u + (uint32_t)(c % 3) * 16384u;
        const uint32_t vb = kb + 8192u;

        float st[8][4];
#pragma unroll
        for (int j = 0; j < 8; j++)
#pragma unroll
            for (int q = 0; q < 4; q++) st[j][q] = 0.f;

#pragma unroll
        for (int ks = 0; ks < 4; ks++) {
#pragma unroll
            for (int g = 0; g < 4; g++) {
                const uint32_t ro = (uint32_t)((g * 16 + b_row) * 128 + ks * 32 + b_col);
                uint32_t kf[4];
                ldsm4(kf, kb + SWZ128(ro));
#pragma unroll
                for (int ns = 0; ns < 2; ns++)
                    mma16816(st[g * 2 + ns], qf[ks], &kf[ns * 2]);
            }
        }

#pragma unroll
        for (int ks = 0; ks < 4; ks++) {
            uint32_t ph[4];
#pragma unroll
            for (int half = 0; half < 2; half++) {
                const float* sA = st[2 * ks + half];
                ph[half * 2 + 0] = ex2h2(packh2(sA[0], sA[1]));
                ph[half * 2 + 1] = ex2h2(packh2(sA[2], sA[3]));
            }
            mma16816(lacc, ph, ones_b);
#pragma unroll
            for (int nt = 0; nt < 4; nt++) {
                const uint32_t ro = (uint32_t)((ks * 16 + vr) * 128 + (nt * 16 + vcol) * 2);
                uint32_t vf[4];
                ldsm4t(vf, vb + SWZ128(ro));
#pragma unroll
                for (int ns = 0; ns < 2; ns++)
                    mma16816(o[nt * 2 + ns], ph, &vf[ns * 2]);
            }
        }

        if (c + 2 < 32) issue_kv(c + 2);
    }

    const float inv0 = 1.0f / lacc[0];
    const float inv1 = 1.0f / lacc[2];
    const int gr0 = grow + wid * 16 + (lid >> 2);
    const int gr1 = gr0 + 8;
#pragma unroll
    for (int j = 0; j < 8; j++) {
        const int col = hoff + j * 8 + (lid & 3) * 2;
        *(uint32_t*)&O16[(size_t)gr0 * 1024 + col] =
            packh2(o[j][0] * inv0, o[j][1] * inv0);
        *(uint32_t*)&O16[(size_t)gr1 * 1024 + col] =
            packh2(o[j][2] * inv1, o[j][3] * inv1);
    }
}

// ---------------------------------------------------------------------------
// Row-wise LayerNorm, warp-per-row (no barriers, no smem).
// ---------------------------------------------------------------------------
__global__ __launch_bounds__(256) void ln_kernel(
    float* __restrict__ y, const float* __restrict__ g, const float* __restrict__ bb)
{
    const int wid = threadIdx.x >> 5, lane = threadIdx.x & 31;
    const int row = blockIdx.x * 8 + wid;
    float4* y4 = (float4*)(y + (size_t)row * D);

    float4 v[8];
    float s = 0.f, q = 0.f;
#pragma unroll
    for (int k = 0; k < 8; k++) {
        v[k] = y4[lane + 32 * k];
        s += v[k].x + v[k].y + v[k].z + v[k].w;
        q += v[k].x * v[k].x + v[k].y * v[k].y + v[k].z * v[k].z + v[k].w * v[k].w;
    }
#pragma unroll
    for (int msk = 16; msk >= 1; msk >>= 1) {
        s += __shfl_xor_sync(0xffffffffu, s, msk);
        q += __shfl_xor_sync(0xffffffffu, q, msk);
    }
    const float mu  = s * (1.0f / D);
    const float var = q * (1.0f / D) - mu * mu;
    const float rinv = rsqrtf(var + 1e-12f);

    const float4* g4 = (const float4*)g;
    const float4* b4 = (const float4*)bb;
#pragma unroll
    for (int k = 0; k < 8; k++) {
        float4 gg = g4[lane + 32 * k];
        float4 bv = b4[lane + 32 * k];
        float4 ov;
        ov.x = (v[k].x - mu) * rinv * gg.x + bv.x;
        ov.y = (v[k].y - mu) * rinv * gg.y + bv.y;
        ov.z = (v[k].z - mu) * rinv * gg.z + bv.z;
        ov.w = (v[k].w - mu) * rinv * gg.w + bv.w;
        y4[lane + 32 * k] = ov;
    }
}

// ---------------------------------------------------------------------------
extern "C" void kernel_launch(void* const* d_in, const int* in_sizes, int n_in,
                              void* d_out, int out_size)
{
    const float* x   = (const float*)d_in[0];
    const float* wq  = (const float*)d_in[1];
    const float* bq  = (const float*)d_in[2];
    const float* wk  = (const float*)d_in[3];
    const float* bk  = (const float*)d_in[4];
    const float* wv  = (const float*)d_in[5];
    const float* bv  = (const float*)d_in[6];
    const float* wo  = (const float*)d_in[7];
    const float* bo  = (const float*)d_in[8];
    const float* lng = (const float*)d_in[9];
    const float* lnb = (const float*)d_in[10];
    float* out = (float*)d_out;

    __half *x16, *q16, *k16, *v16, *o16, *w;
    cudaGetSymbolAddress((void**)&x16, g_x16);
    cudaGetSymbolAddress((void**)&q16, g_q16);
    cudaGetSymbolAddress((void**)&k16, g_k16);
    cudaGetSymbolAddress((void**)&v16, g_v16);
    cudaGetSymbolAddress((void**)&o16, g_o16);
    cudaGetSymbolAddress((void**)&w, g_w);

    // Fused preprocessing: 4 weight transposes + x convert in ONE launch
    dim3 pthr(32, 8), pgrd(D / 32, D / 32, 5);
    prep_kernel<<<pgrd, pthr>>>(wq, wk, wv, wo, w, (const float4*)x, (h4*)x16);

    cudaFuncSetAttribute(gemm_qkv_kernel,
                         cudaFuncAttributeMaxDynamicSharedMemorySize, GEMM_SMEM);
    cudaFuncSetAttribute(gemm_out_kernel,
                         cudaFuncAttributeMaxDynamicSharedMemorySize, GEMM_SMEM);

    gemm_qkv_kernel<<<dim3(3 * D / 128, M_ROWS / 128), 256, GEMM_SMEM>>>(
        x16, w, bq, bk, bv, q16, k16, v16);

    cudaFuncSetAttribute(attn_hmma_kernel,
                         cudaFuncAttributeMaxDynamicSharedMemorySize, ATT_SMEM);
    attn_hmma_kernel<<<dim3(S / 128, B * H), 256, ATT_SMEM>>>(
        q16, k16, v16, o16);

    gemm_out_kernel<<<dim3(D / 128, M_ROWS / 128), 256, GEMM_SMEM>>>(
        o16, w + 3 * (size_t)D * D, bo, out);

    ln_kernel<<<M_ROWS / 8, 256>>>(out, lng, lnb);
}

// round 17
// speedup vs baseline: 1.1034x; 1.0265x over previous
#include <cuda_runtime.h>
#include <cuda_fp16.h>
#include <cstdint>
#include <math.h>

// Problem constants
static constexpr int B  = 4;
static constexpr int S  = 2048;
static constexpr int D  = 1024;
static constexpr int H  = 16;
static constexpr int M_ROWS = B * S;       // 8192

// Q pre-scale: (1/sqrt(64)) * log2(e)  -> scores arrive in log2 domain
#define QSCALE 0.18033688011112042f

// ---------------------------------------------------------------------------
// Scratch (device globals)
// ---------------------------------------------------------------------------
__device__ __half g_x16[M_ROWS * D];
__device__ __half g_q16[M_ROWS * D];
__device__ __half g_k16[M_ROWS * D];
__device__ __half g_v16[M_ROWS * D];
__device__ __half g_o16[M_ROWS * D];
__device__ __half g_w[4][D * D];           // wq,wk,wv contiguous => N=3072 view; [3]=wo

struct __align__(8) h4 { __half v[4]; };

// ---------------------------------------------------------------------------
// Portable-PTX helpers (compute_103-safe)
// ---------------------------------------------------------------------------
__device__ __forceinline__ uint32_t smem_to_u32(const void* p) {
    uint32_t a;
    asm("{ .reg .u64 tmp; cvta.to.shared.u64 tmp, %1; cvt.u32.u64 %0, tmp; }"
        : "=r"(a) : "l"(p));
    return a;
}
__device__ __forceinline__ void ldsm4(uint32_t* r, uint32_t addr) {
    asm volatile("ldmatrix.sync.aligned.m8n8.x4.shared.b16 {%0,%1,%2,%3}, [%4];"
        : "=r"(r[0]), "=r"(r[1]), "=r"(r[2]), "=r"(r[3]) : "r"(addr));
}
__device__ __forceinline__ void ldsm4t(uint32_t* r, uint32_t addr) {
    asm volatile("ldmatrix.sync.aligned.m8n8.x4.trans.shared.b16 {%0,%1,%2,%3}, [%4];"
        : "=r"(r[0]), "=r"(r[1]), "=r"(r[2]), "=r"(r[3]) : "r"(addr));
}
__device__ __forceinline__ void mma16816(float* c, const uint32_t* a, const uint32_t* b) {
    asm volatile("mma.sync.aligned.m16n8k16.row.col.f32.f16.f16.f32 "
        "{%0,%1,%2,%3}, {%4,%5,%6,%7}, {%8,%9}, {%0,%1,%2,%3};"
        : "+f"(c[0]), "+f"(c[1]), "+f"(c[2]), "+f"(c[3])
        : "r"(a[0]), "r"(a[1]), "r"(a[2]), "r"(a[3]), "r"(b[0]), "r"(b[1]));
}
__device__ __forceinline__ void cp_async16(uint32_t dst, const void* src) {
    asm volatile("cp.async.cg.shared.global [%0], [%1], 16;" :: "r"(dst), "l"(src));
}
#define CP_COMMIT() asm volatile("cp.async.commit_group;" ::: "memory")
#define CP_WAIT(n)  asm volatile("cp.async.wait_group %0;" :: "n"(n) : "memory")
#define SWZ128(off) ((off) ^ (((off) >> 3) & 0x70))

__device__ __forceinline__ uint32_t packh2(float a, float b) {
    __half2 p = __floats2half2_rn(a, b);
    return *(uint32_t*)&p;
}
__device__ __forceinline__ uint32_t ex2h2(uint32_t x) {
    uint32_t r;
    asm("ex2.approx.f16x2 %0, %1;" : "=r"(r) : "r"(x));
    return r;
}

// ---------------------------------------------------------------------------
// Fused preprocessing: grid.z 0..3 -> transpose+round weight z; z==4 -> convert x
// ---------------------------------------------------------------------------
__global__ __launch_bounds__(256) void prep_kernel(
    const float* __restrict__ W0, const float* __restrict__ W1,
    const float* __restrict__ W2, const float* __restrict__ W3,
    __half* __restrict__ T,
    const float4* __restrict__ X, h4* __restrict__ X16)
{
    const int z = blockIdx.z;
    if (z == 4) {
        const int bid = blockIdx.y * gridDim.x + blockIdx.x;   // 0..1023
        const int t = threadIdx.y * 32 + threadIdx.x;          // 0..255
        int base = bid * 2048 + t;
#pragma unroll
        for (int it = 0; it < 8; it++) {
            float4 v = X[base + it * 256];
            h4 h;
            h.v[0] = __float2half_rn(v.x);
            h.v[1] = __float2half_rn(v.y);
            h.v[2] = __float2half_rn(v.z);
            h.v[3] = __float2half_rn(v.w);
            X16[base + it * 256] = h;
        }
        return;
    }
    __shared__ float tile[32][33];
    const float* W = (z == 0) ? W0 : (z == 1) ? W1 : (z == 2) ? W2 : W3;
    __half* Tz = T + (size_t)z * D * D;
    const int bx = blockIdx.x * 32;
    const int by = blockIdx.y * 32;
    const int tx = threadIdx.x, ty = threadIdx.y;
#pragma unroll
    for (int i = ty; i < 32; i += 8)
        tile[i][tx] = W[(size_t)(by + i) * D + bx + tx];
    __syncthreads();
#pragma unroll
    for (int i = ty; i < 32; i += 8)
        Tz[(size_t)(bx + i) * D + by + tx] = __float2half_rn(tile[tx][i]);
}

// ---------------------------------------------------------------------------
// Shared GEMM mainloop: 128x128 CTA tile, BK=64 (SW128 rows), 3-stage
// pipeline, ONE __syncthreads per iteration, issue-after-consume.
// Per stage (32 KB): A(16K) B(16K); 3 stages = 96 KB; 2 CTAs/SM (192 KB).
// ---------------------------------------------------------------------------
static constexpr int GEMM_SMEM = 3 * 32768;   // 98304

__device__ __forceinline__ void gemm_issue_chunk(
    uint32_t sbase, const __half* const* srcs, int t, int c)
{
    const int k0 = c * 64;
    const uint32_t base = (uint32_t)(c % 3) * 32768u;
#pragma unroll
    for (int ld = 0; ld < 8; ld++) {
        const int j = t + 256 * ld;            // 0..2047
        const int tile = j >> 10;              // 0=A, 1=B
        const int jj = j & 1023;
        const int r = jj >> 3, c16 = jj & 7;   // 128 rows x 8 16B-chunks
        const __half* src = srcs[tile] + (size_t)r * 1024 + k0 + c16 * 8;
        const uint32_t dst = sbase + base + (uint32_t)tile * 16384u +
                             SWZ128((uint32_t)(r * 128 + c16 * 16));
        cp_async16(dst, src);
    }
    CP_COMMIT();
}

__device__ __forceinline__ void gemm_mainloop(
    uint32_t sbase, const __half* const* srcs, int t, float acc[2][8][4])
{
    const int wid = t >> 5, lid = t & 31;
    const int warp_m = wid & 3;
    const int warp_n = wid >> 2;

    gemm_issue_chunk(sbase, srcs, t, 0);
    gemm_issue_chunk(sbase, srcs, t, 1);

    const int a_row  = lid & 15;
    const int a_colb = (lid >> 4) * 16;
    const int b_row  = ((lid >> 4) & 1) * 8 + (lid & 7);
    const int b_colb = ((lid >> 3) & 1) * 16;

    for (int c = 0; c < 16; c++) {
        if (c + 1 < 16) CP_WAIT(1); else CP_WAIT(0);
        __syncthreads();

        const uint32_t a_b = sbase + (uint32_t)(c % 3) * 32768u;
        const uint32_t b_b = a_b + 16384u;

#pragma unroll
        for (int ks = 0; ks < 4; ks++) {
            const int kb = ks * 32;
            uint32_t af[2][4];
#pragma unroll
            for (int mt = 0; mt < 2; mt++) {
                const uint32_t ro = (uint32_t)((warp_m * 32 + mt * 16 + a_row) * 128
                                               + kb + a_colb);
                ldsm4(af[mt], a_b + SWZ128(ro));
            }
#pragma unroll
            for (int g = 0; g < 4; g++) {
                const uint32_t ro = (uint32_t)((warp_n * 64 + g * 16 + b_row) * 128
                                               + kb + b_colb);
                uint32_t bf[4];
                ldsm4(bf, b_b + SWZ128(ro));
#pragma unroll
                for (int mt = 0; mt < 2; mt++)
#pragma unroll
                    for (int ns = 0; ns < 2; ns++)
                        mma16816(acc[mt][g * 2 + ns], af[mt], &bf[ns * 2]);
            }
        }
        if (c + 2 < 16) gemm_issue_chunk(sbase, srcs, t, c + 2);
    }
}

// ---------------------------------------------------------------------------
// Fused QKV GEMM: N=3072. Q scaled by QSCALE (1/8 * log2 e); fp16 outputs.
// grid = (24, 64)
// ---------------------------------------------------------------------------
__global__ __launch_bounds__(256, 2)
void gemm_qkv_kernel(const __half* __restrict__ X16,
                     const __half* __restrict__ W,
                     const float* __restrict__ bq,
                     const float* __restrict__ bk,
                     const float* __restrict__ bv,
                     __half* __restrict__ Q16,
                     __half* __restrict__ K16, __half* __restrict__ V16)
{
    extern __shared__ __align__(1024) char smem[];
    const uint32_t sbase = smem_to_u32(smem);
    const int t = threadIdx.x;
    const int wid = t >> 5, lid = t & 31;
    const int warp_m = wid & 3, warp_n = wid >> 2;
    const int m0 = blockIdx.y * 128;
    const int n0g = blockIdx.x * 128;          // 0..2944
    const int seg = n0g >> 10;                 // 0=Q, 1=K, 2=V
    const int n0 = n0g & 1023;

    const float* bias = (seg == 0) ? bq : (seg == 1) ? bk : bv;
    __half* Cd = (seg == 0) ? Q16 : (seg == 1) ? K16 : V16;
    const float scale = (seg == 0) ? QSCALE : 1.0f;

    const __half* srcs[2];
    srcs[0] = X16 + (size_t)m0 * 1024;
    srcs[1] = W   + (size_t)n0g * 1024;

    float acc[2][8][4];
#pragma unroll
    for (int mt = 0; mt < 2; mt++)
#pragma unroll
        for (int nt = 0; nt < 8; nt++)
#pragma unroll
            for (int j = 0; j < 4; j++) acc[mt][nt][j] = 0.f;

    gemm_mainloop(sbase, srcs, t, acc);

#pragma unroll
    for (int mt = 0; mt < 2; mt++) {
        const int r0 = m0 + warp_m * 32 + mt * 16 + (lid >> 2);
#pragma unroll
        for (int nt = 0; nt < 8; nt++) {
            const int col = n0 + warp_n * 64 + nt * 8 + (lid & 3) * 2;
            float2 bv2 = *(const float2*)&bias[col];
            const float* a4 = acc[mt][nt];
            *(uint32_t*)&Cd[(size_t)r0 * 1024 + col] =
                packh2((a4[0] + bv2.x) * scale, (a4[1] + bv2.y) * scale);
            *(uint32_t*)&Cd[(size_t)(r0 + 8) * 1024 + col] =
                packh2((a4[2] + bv2.x) * scale, (a4[3] + bv2.y) * scale);
        }
    }
}

// ---------------------------------------------------------------------------
// Out-proj GEMM: N=1024, fp32 out + bias. grid = (8, 64)
// ---------------------------------------------------------------------------
__global__ __launch_bounds__(256, 2)
void gemm_out_kernel(const __half* __restrict__ A16,
                     const __half* __restrict__ W,
                     const float* __restrict__ bias,
                     float* __restrict__ C)
{
    extern __shared__ __align__(1024) char smem[];
    const uint32_t sbase = smem_to_u32(smem);
    const int t = threadIdx.x;
    const int wid = t >> 5, lid = t & 31;
    const int warp_m = wid & 3, warp_n = wid >> 2;
    const int m0 = blockIdx.y * 128;
    const int n0 = blockIdx.x * 128;

    const __half* srcs[2];
    srcs[0] = A16 + (size_t)m0 * 1024;
    srcs[1] = W   + (size_t)n0 * 1024;

    float acc[2][8][4];
#pragma unroll
    for (int mt = 0; mt < 2; mt++)
#pragma unroll
        for (int nt = 0; nt < 8; nt++)
#pragma unroll
            for (int j = 0; j < 4; j++) acc[mt][nt][j] = 0.f;

    gemm_mainloop(sbase, srcs, t, acc);

#pragma unroll
    for (int mt = 0; mt < 2; mt++) {
        const int r0 = m0 + warp_m * 32 + mt * 16 + (lid >> 2);
#pragma unroll
        for (int nt = 0; nt < 8; nt++) {
            const int col = n0 + warp_n * 64 + nt * 8 + (lid & 3) * 2;
            float2 bv2 = *(const float2*)&bias[col];
            const float* a4 = acc[mt][nt];
            *(float2*)&C[(size_t)r0 * 1024 + col] =
                make_float2(a4[0] + bv2.x, a4[1] + bv2.y);
            *(float2*)&C[(size_t)(r0 + 8) * 1024 + col] =
                make_float2(a4[2] + bv2.x, a4[3] + bv2.y);
        }
    }
}

// ---------------------------------------------------------------------------
// HMMA attention: R10 shape (16 q-rows/warp, 2 CTAs/SM, 3-stage 64-key
// pipeline) with per-key-group restructured inner loop:
//   group g: 8 score MMAs -> ex2 -> lacc-MMA -> 8 PV MMAs
// Live score registers 32 -> 8; same ops, same accumulation order
// (bit-identical numerics), shorter dependency chains for the scheduler.
// ---------------------------------------------------------------------------
static constexpr int ATT_SMEM = 16384 + 3 * 16384;   // 65536

__global__ __launch_bounds__(256, 2)
void attn_hmma_kernel(const __half* __restrict__ Q16,
                      const __half* __restrict__ K16,
                      const __half* __restrict__ V16,
                      __half* __restrict__ O16)
{
    extern __shared__ __align__(1024) char smem[];
    const uint32_t sbase = smem_to_u32(smem);
    const int t = threadIdx.x;
    const int wid = t >> 5, lid = t & 31;
    const int qt = blockIdx.x * 128;
    const int bh = blockIdx.y;
    const int b = bh >> 4, h = bh & 15;
    const int grow = b * S + qt;
    const int hoff = h * 64;

#pragma unroll
    for (int ld = 0; ld < 4; ld++) {
        const int j = t + 256 * ld;           // 0..1023
        const int r = j >> 3, c16 = j & 7;
        const __half* src = Q16 + (size_t)(grow + r) * 1024 + hoff + c16 * 8;
        const uint32_t dst = sbase + SWZ128((uint32_t)(r * 128 + c16 * 16));
        cp_async16(dst, src);
    }
    CP_COMMIT();

    const __half* ksrc = K16 + (size_t)b * S * 1024 + hoff;
    const __half* vsrc = V16 + (size_t)b * S * 1024 + hoff;

    auto issue_kv = [&](int c) {
        const int k0 = c * 64;
        const uint32_t base = 16384u + (uint32_t)(c % 3) * 16384u;
#pragma unroll
        for (int ld = 0; ld < 4; ld++) {
            const int j = t + 256 * ld;       // 0..1023
            const int tile = j >> 9;          // 0=K, 1=V
            const int jj = j & 511;
            const int r = jj >> 3, c16 = jj & 7;
            const __half* src = (tile ? vsrc : ksrc) + (size_t)(k0 + r) * 1024 + c16 * 8;
            const uint32_t dst = sbase + base + (uint32_t)tile * 8192u +
                                 SWZ128((uint32_t)(r * 128 + c16 * 16));
            cp_async16(dst, src);
        }
        CP_COMMIT();
    };

    issue_kv(0);
    issue_kv(1);
    CP_WAIT(2);          // Q group done
    __syncthreads();

    const int a_row = lid & 15;
    const int a_col = (lid >> 4) * 16;
    uint32_t qf[4][4];
#pragma unroll
    for (int ks = 0; ks < 4; ks++) {
        const uint32_t ro = (uint32_t)((wid * 16 + a_row) * 128 + ks * 32 + a_col);
        ldsm4(qf[ks], sbase + SWZ128(ro));
    }

    float o[8][4];
#pragma unroll
    for (int j = 0; j < 8; j++)
#pragma unroll
        for (int q = 0; q < 4; q++) o[j][q] = 0.f;
    float lacc[4] = {0.f, 0.f, 0.f, 0.f};
    const uint32_t ones_b[2] = {0x3C003C00u, 0x3C003C00u};

    const int b_row = ((lid >> 4) & 1) * 8 + (lid & 7);
    const int b_col = ((lid >> 3) & 1) * 16;
    const int g2 = lid >> 3;
    const int vr = (g2 & 1) * 8 + (lid & 7);
    const int vcol = (g2 >> 1) * 8;

    for (int c = 0; c < 32; c++) {
        if (c + 1 < 32) CP_WAIT(1); else CP_WAIT(0);
        __syncthreads();

        const uint32_t kb = sbase + 16384u + (uint32_t)(c % 3) * 16384u;
        const uint32_t vb = kb + 8192u;

        // ---- per key-group: scores -> ex2 -> lacc -> PV ----
#pragma unroll
        for (int g = 0; g < 4; g++) {
            float st0[4] = {0.f, 0.f, 0.f, 0.f};
            float st1[4] = {0.f, 0.f, 0.f, 0.f};
#pragma unroll
            for (int ks = 0; ks < 4; ks++) {
                const uint32_t ro = (uint32_t)((g * 16 + b_row) * 128 + ks * 32 + b_col);
                uint32_t kf[4];
                ldsm4(kf, kb + SWZ128(ro));
                mma16816(st0, qf[ks], &kf[0]);
                mma16816(st1, qf[ks], &kf[2]);
            }

            uint32_t ph[4];
            ph[0] = ex2h2(packh2(st0[0], st0[1]));
            ph[1] = ex2h2(packh2(st0[2], st0[3]));
            ph[2] = ex2h2(packh2(st1[0], st1[1]));
            ph[3] = ex2h2(packh2(st1[2], st1[3]));
            mma16816(lacc, ph, ones_b);

#pragma unroll
            for (int nt = 0; nt < 4; nt++) {
                const uint32_t ro = (uint32_t)((g * 16 + vr) * 128 + (nt * 16 + vcol) * 2);
                uint32_t vf[4];
                ldsm4t(vf, vb + SWZ128(ro));
                mma16816(o[nt * 2 + 0], ph, &vf[0]);
                mma16816(o[nt * 2 + 1], ph, &vf[2]);
            }
        }

        if (c + 2 < 32) issue_kv(c + 2);
    }

    const float inv0 = 1.0f / lacc[0];
    const float inv1 = 1.0f / lacc[2];
    const int gr0 = grow + wid * 16 + (lid >> 2);
    const int gr1 = gr0 + 8;
#pragma unroll
    for (int j = 0; j < 8; j++) {
        const int col = hoff + j * 8 + (lid & 3) * 2;
        *(uint32_t*)&O16[(size_t)gr0 * 1024 + col] =
            packh2(o[j][0] * inv0, o[j][1] * inv0);
        *(uint32_t*)&O16[(size_t)gr1 * 1024 + col] =
            packh2(o[j][2] * inv1, o[j][3] * inv1);
    }
}

// ---------------------------------------------------------------------------
// Row-wise LayerNorm, warp-per-row (no barriers, no smem).
// ---------------------------------------------------------------------------
__global__ __launch_bounds__(256) void ln_kernel(
    float* __restrict__ y, const float* __restrict__ g, const float* __restrict__ bb)
{
    const int wid = threadIdx.x >> 5, lane = threadIdx.x & 31;
    const int row = blockIdx.x * 8 + wid;
    float4* y4 = (float4*)(y + (size_t)row * D);

    float4 v[8];
    float s = 0.f, q = 0.f;
#pragma unroll
    for (int k = 0; k < 8; k++) {
        v[k] = y4[lane + 32 * k];
        s += v[k].x + v[k].y + v[k].z + v[k].w;
        q += v[k].x * v[k].x + v[k].y * v[k].y + v[k].z * v[k].z + v[k].w * v[k].w;
    }
#pragma unroll
    for (int msk = 16; msk >= 1; msk >>= 1) {
        s += __shfl_xor_sync(0xffffffffu, s, msk);
        q += __shfl_xor_sync(0xffffffffu, q, msk);
    }
    const float mu  = s * (1.0f / D);
    const float var = q * (1.0f / D) - mu * mu;
    const float rinv = rsqrtf(var + 1e-12f);

    const float4* g4 = (const float4*)g;
    const float4* b4 = (const float4*)bb;
#pragma unroll
    for (int k = 0; k < 8; k++) {
        float4 gg = g4[lane + 32 * k];
        float4 bv = b4[lane + 32 * k];
        float4 ov;
        ov.x = (v[k].x - mu) * rinv * gg.x + bv.x;
        ov.y = (v[k].y - mu) * rinv * gg.y + bv.y;
        ov.z = (v[k].z - mu) * rinv * gg.z + bv.z;
        ov.w = (v[k].w - mu) * rinv * gg.w + bv.w;
        y4[lane + 32 * k] = ov;
    }
}

// ---------------------------------------------------------------------------
extern "C" void kernel_launch(void* const* d_in, const int* in_sizes, int n_in,
                              void* d_out, int out_size)
{
    const float* x   = (const float*)d_in[0];
    const float* wq  = (const float*)d_in[1];
    const float* bq  = (const float*)d_in[2];
    const float* wk  = (const float*)d_in[3];
    const float* bk  = (const float*)d_in[4];
    const float* wv  = (const float*)d_in[5];
    const float* bv  = (const float*)d_in[6];
    const float* wo  = (const float*)d_in[7];
    const float* bo  = (const float*)d_in[8];
    const float* lng = (const float*)d_in[9];
    const float* lnb = (const float*)d_in[10];
    float* out = (float*)d_out;

    __half *x16, *q16, *k16, *v16, *o16, *w;
    cudaGetSymbolAddress((void**)&x16, g_x16);
    cudaGetSymbolAddress((void**)&q16, g_q16);
    cudaGetSymbolAddress((void**)&k16, g_k16);
    cudaGetSymbolAddress((void**)&v16, g_v16);
    cudaGetSymbolAddress((void**)&o16, g_o16);
    cudaGetSymbolAddress((void**)&w, g_w);

    dim3 pthr(32, 8), pgrd(D / 32, D / 32, 5);
    prep_kernel<<<pgrd, pthr>>>(wq, wk, wv, wo, w, (const float4*)x, (h4*)x16);

    cudaFuncSetAttribute(gemm_qkv_kernel,
                         cudaFuncAttributeMaxDynamicSharedMemorySize, GEMM_SMEM);
    cudaFuncSetAttribute(gemm_out_kernel,
                         cudaFuncAttributeMaxDynamicSharedMemorySize, GEMM_SMEM);

    gemm_qkv_kernel<<<dim3(3 * D / 128, M_ROWS / 128), 256, GEMM_SMEM>>>(
        x16, w, bq, bk, bv, q16, k16, v16);

    cudaFuncSetAttribute(attn_hmma_kernel,
                         cudaFuncAttributeMaxDynamicSharedMemorySize, ATT_SMEM);
    attn_hmma_kernel<<<dim3(S / 128, B * H), 256, ATT_SMEM>>>(
        q16, k16, v16, o16);

    gemm_out_kernel<<<dim3(D / 128, M_ROWS / 128), 256, GEMM_SMEM>>>(
        o16, w + 3 * (size_t)D * D, bo, out);

    ln_kernel<<<M_ROWS / 8, 256>>>(out, lng, lnb);
}